// round 12
// baseline (speedup 1.0000x reference)
#include <cuda_runtime.h>

#define NPTS    2048
#define NPAIR   (NPTS/2)             // 1024 point-pairs
#define UPR     10
#define NJIT    (NPTS*UPR)           // 20480 jittered queries
#define QTOT    (NJIT + NPTS)        // 22528
#define KNN     5
#define T1      256                  // 8 warps: 4 query-groups x 2 half-warps
#define QPB     128                  // queries per block
#define GX1     (QTOT/QPB)           // 176  (x2 clouds in grid.y)
#define HPAIRS  (NPAIR/2)            // 512 pairs per half-warp
#define NB2     (QTOT/256)           // 88
#define EPS_D   1e-8f
#define EPS_N   1e-10f
#define BETA    3.0f
#define STDV    0.05f
#define IDXMASK 0xFFFFF800u          // high 21 bits = d2, low 11 bits = point index

__device__ float4 g_grad[2][QTOT];   // normalized weighted gradient per (cloud,query)
__device__ float  g_partial[NB2];

__device__ __forceinline__ void ins5key(int key, int& s0, int& s1, int& s2, int& s3, int& s4) {
    s4 = key;
    int a;
    a = min(s3, s4); s4 = max(s3, s4); s3 = a;
    a = min(s2, s3); s3 = max(s2, s3); s2 = a;
    a = min(s1, s2); s2 = max(s1, s2); s1 = a;
    a = min(s0, s1); s1 = max(s0, s1); s0 = a;
}

__device__ __forceinline__ unsigned long long packf2(float lo, float hi) {
    unsigned long long r;
    asm("mov.b64 %0, {%1, %2};" : "=l"(r) : "f"(lo), "f"(hi));
    return r;
}

__global__ __launch_bounds__(T1)
void knn_main(const float* __restrict__ src,
              const float* __restrict__ tgt,
              const float* __restrict__ noise)
{
    // Pair-SoA: sC[2p] = {x0,x1,y0,y1}, sC[2p+1] = {z0,z1,w0,w1}
    __shared__ float4 sC[NPTS];              // 32 KB
    __shared__ int    sKeys[4][KNN][32];     // 2.5 KB merge buffer

    const int tid   = threadIdx.x;
    const int lane  = tid & 31;
    const int warp  = tid >> 5;
    const int group = warp >> 1;             // 0..3 : which 32-query group
    const int half  = warp & 1;              // 0/1  : which half of point range
    const int cloud = blockIdx.y;
    const float* __restrict__ pts = cloud ? src : tgt;

    for (int i = tid; i < NPTS; i += T1) {
        float x = pts[3*i], y = pts[3*i+1], z = pts[3*i+2];
        float w = fmaf(x, x, fmaf(y, y, z * z));
        int pj = i >> 1, h = i & 1;
        float* base = (float*)&sC[2 * pj];
        base[0 + h] = x;
        base[2 + h] = y;
        base[4 + h] = z;
        base[6 + h] = w;
    }
    __syncthreads();

    // One query per lane.
    const int qi = blockIdx.x * QPB + (group << 5) + lane;
    float qx, qy, qz;
    if (qi < NJIT) {
        int m = qi / UPR;
        qx = fmaf(noise[3*qi + 0], STDV, tgt[3*m + 0]);
        qy = fmaf(noise[3*qi + 1], STDV, tgt[3*m + 1]);
        qz = fmaf(noise[3*qi + 2], STDV, tgt[3*m + 2]);
    } else {
        int m = qi - NJIT;
        qx = src[3*m + 0]; qy = src[3*m + 1]; qz = src[3*m + 2];
    }
    const float qx2 = -2.0f * qx, qy2 = -2.0f * qy, qz2 = -2.0f * qz;
    const float q2  = fmaf(qx, qx, fmaf(qy, qy, qz * qz));
    const unsigned long long qxp = packf2(qx2, qx2);
    const unsigned long long qyp = packf2(qy2, qy2);
    const unsigned long long qzp = packf2(qz2, qz2);

    int s0 = 0x7F000000, s1 = 0x7F000001, s2 = 0x7F000002,
        s3 = 0x7F000003, s4 = 0x7F000004;
    float thr = __int_as_float(s4) - q2;   // threshold in r-space

    // Broadcast scan: ALL lanes read the SAME pair (uniform address -> 1 smem
    // access serves the warp). This warp covers pairs [half*512, half*512+512).
    const ulonglong2* pc = reinterpret_cast<const ulonglong2*>(sC) + (half << 10);
    const int joff = (half << 9) * 2;     // point index offset of this half

#pragma unroll 4
    for (int k = 0; k < HPAIRS; ++k) {
        ulonglong2 A = pc[2 * k];        // {x-pair, y-pair}
        ulonglong2 B = pc[2 * k + 1];    // {z-pair, w-pair}
        unsigned long long r01;
        asm("fma.rn.f32x2 %0, %1, %2, %3;" : "=l"(r01) : "l"(B.x), "l"(qzp), "l"(B.y));
        asm("fma.rn.f32x2 %0, %1, %2, %3;" : "=l"(r01) : "l"(A.y), "l"(qyp), "l"(r01));
        asm("fma.rn.f32x2 %0, %1, %2, %3;" : "=l"(r01) : "l"(A.x), "l"(qxp), "l"(r01));
        float r0, r1;
        asm("mov.b64 {%0, %1}, %2;" : "=f"(r0), "=f"(r1) : "l"(r01));

        if (fminf(r0, r1) < thr) {
            int jbase = joff + (k << 1);
            if (r0 < thr) {
                float d2 = r0 + q2;
                int key = (int)((__float_as_uint(d2) & IDXMASK) | (unsigned)jbase);
                ins5key(key, s0, s1, s2, s3, s4);
                thr = __int_as_float(s4) - q2;
            }
            if (r1 < thr) {
                float d2 = r1 + q2;
                int key = (int)((__float_as_uint(d2) & IDXMASK) | (unsigned)(jbase + 1));
                ins5key(key, s0, s1, s2, s3, s4);
                thr = __int_as_float(s4) - q2;
            }
        }
    }

    // Cross-warp merge: odd half publishes its 5 keys; even half merges + finishes.
    if (half) {
        sKeys[group][0][lane] = s0;
        sKeys[group][1][lane] = s1;
        sKeys[group][2][lane] = s2;
        sKeys[group][3][lane] = s3;
        sKeys[group][4][lane] = s4;
    }
    __syncthreads();

    if (!half) {
#pragma unroll
        for (int r = 0; r < KNN; ++r) {
            int o = sKeys[group][r][lane];
            if (o < s4) ins5key(o, s0, s1, s2, s3, s4);
        }

        // Exact epilogue (bit-identical to R7's: same selected key set).
        float aw = 0.f, gx = 0.f, gy = 0.f, gz = 0.f;
        int keys[KNN] = {s0, s1, s2, s3, s4};
#pragma unroll
        for (int kk = 0; kk < KNN; ++kk) {
            int idx = keys[kk] & 2047;
            int pj = idx >> 1, h = idx & 1;
            const float* base = (const float*)&sC[2 * pj];
            float x = base[0 + h], y = base[2 + h], z = base[4 + h];
            float dx = qx - x, dy = qy - y, dz = qz - z;
            float d2 = fmaf(dx, dx, fmaf(dy, dy, dz * dz));
            float w  = 1.0f / (d2 + EPS_D);
            aw += w;
            gx = fmaf(dx, w, gx);
            gy = fmaf(dy, w, gy);
            gz = fmaf(dz, w, gz);
        }
        float inv = 1.0f / aw;
        g_grad[cloud][qi] = make_float4(gx * inv, gy * inv, gz * inv, 0.f);
    }
}

__global__ __launch_bounds__(256)
void combine_kernel()
{
    __shared__ float sh[8];
    const int tid = threadIdx.x;
    const int qi  = blockIdx.x * 256 + tid;

    float4 gT = g_grad[0][qi];
    float4 gS = g_grad[1][qi];

    float axT = gT.x + EPS_N, ayT = gT.y + EPS_N, azT = gT.z + EPS_N;
    float axS = gS.x + EPS_N, ayS = gS.y + EPS_N, azS = gS.z + EPS_N;
    float uT = sqrtf(fmaf(axT, axT, fmaf(ayT, ayT, azT * azT)));
    float uS = sqrtf(fmaf(axS, axS, fmaf(ayS, ayS, azS * azS)));

    float e1 = fabsf(uT - uS);
    float e2 = fabsf(gS.x - gT.x) + fabsf(gS.y - gT.y) + fabsf(gS.z - gT.z);
    float t  = e1 + e2;
    float v  = t * __expf(-BETA * t);

#pragma unroll
    for (int o = 16; o > 0; o >>= 1) v += __shfl_down_sync(0xFFFFFFFFu, v, o);
    if ((tid & 31) == 0) sh[tid >> 5] = v;
    __syncthreads();
    if (tid == 0) {
        float s = 0.f;
#pragma unroll
        for (int w = 0; w < 8; ++w) s += sh[w];
        g_partial[blockIdx.x] = s;
    }
}

__global__ void final_reduce(float* __restrict__ out)
{
    __shared__ float sh[4];
    int tid = threadIdx.x;   // 128
    float v = (tid < NB2) ? g_partial[tid] : 0.f;
#pragma unroll
    for (int o = 16; o > 0; o >>= 1) v += __shfl_down_sync(0xFFFFFFFFu, v, o);
    if ((tid & 31) == 0) sh[tid >> 5] = v;
    __syncthreads();
    if (tid == 0) {
        float s = sh[0] + sh[1] + sh[2] + sh[3];
        out[0] = s * (1.0f / (float)QTOT);
    }
}

extern "C" void kernel_launch(void* const* d_in, const int* in_sizes, int n_in,
                              void* d_out, int out_size)
{
    const float* src   = (const float*)d_in[0];
    const float* tgt   = (const float*)d_in[1];
    const float* noise = (const float*)d_in[2];
    (void)in_sizes; (void)n_in; (void)out_size;

    knn_main<<<dim3(GX1, 2), T1>>>(src, tgt, noise);
    combine_kernel<<<NB2, 256>>>();
    final_reduce<<<1, 128>>>((float*)d_out);
}

// round 13
// speedup vs baseline: 1.1742x; 1.1742x over previous
#include <cuda_runtime.h>

#define NPTS    2048
#define NPAIR   (NPTS/2)             // 1024 point-pairs
#define UPR     10
#define NJIT    (NPTS*UPR)           // 20480 jittered queries
#define QTOT    (NJIT + NPTS)        // 22528
#define KNN     5
#define T1      256                  // 8 warps: 2 query-groups x 4 quarter-warps
#define QPB     64                   // queries per block
#define GX1     (QTOT/QPB)           // 352  (x2 clouds in grid.y)
#define QPAIRS  (NPAIR/4)            // 256 pairs per quarter-warp
#define NB2     (QTOT/256)           // 88
#define EPS_D   1e-8f
#define EPS_N   1e-10f
#define BETA    3.0f
#define STDV    0.05f
#define IDXMASK 0xFFFFF800u          // high 21 bits = d2, low 11 bits = point index

__device__ float4 g_grad[2][QTOT];   // normalized weighted gradient per (cloud,query)
__device__ float  g_partial[NB2];

__device__ __forceinline__ void ins5key(int key, int& s0, int& s1, int& s2, int& s3, int& s4) {
    s4 = key;
    int a;
    a = min(s3, s4); s4 = max(s3, s4); s3 = a;
    a = min(s2, s3); s3 = max(s2, s3); s2 = a;
    a = min(s1, s2); s2 = max(s1, s2); s1 = a;
    a = min(s0, s1); s1 = max(s0, s1); s0 = a;
}

__device__ __forceinline__ unsigned long long packf2(float lo, float hi) {
    unsigned long long r;
    asm("mov.b64 %0, {%1, %2};" : "=l"(r) : "f"(lo), "f"(hi));
    return r;
}

__global__ __launch_bounds__(T1)
void knn_main(const float* __restrict__ src,
              const float* __restrict__ tgt,
              const float* __restrict__ noise)
{
    // Pair-SoA: sC[2p] = {x0,x1,y0,y1}, sC[2p+1] = {z0,z1,w0,w1}
    __shared__ float4 sC[NPTS];              // 32 KB
    __shared__ int    sKeys[2][3][KNN][32];  // 3.75 KB merge buffer

    const int tid   = threadIdx.x;
    const int lane  = tid & 31;
    const int warp  = tid >> 5;
    const int group = warp >> 2;             // 0..1 : which 32-query group
    const int quart = warp & 3;              // 0..3 : which quarter of point range
    const int cloud = blockIdx.y;
    const float* __restrict__ pts = cloud ? src : tgt;

    for (int i = tid; i < NPTS; i += T1) {
        float x = pts[3*i], y = pts[3*i+1], z = pts[3*i+2];
        float w = fmaf(x, x, fmaf(y, y, z * z));
        int pj = i >> 1, h = i & 1;
        float* base = (float*)&sC[2 * pj];
        base[0 + h] = x;
        base[2 + h] = y;
        base[4 + h] = z;
        base[6 + h] = w;
    }
    __syncthreads();

    // One query per lane.
    const int qi = blockIdx.x * QPB + (group << 5) + lane;
    float qx, qy, qz;
    if (qi < NJIT) {
        int m = qi / UPR;
        qx = fmaf(noise[3*qi + 0], STDV, tgt[3*m + 0]);
        qy = fmaf(noise[3*qi + 1], STDV, tgt[3*m + 1]);
        qz = fmaf(noise[3*qi + 2], STDV, tgt[3*m + 2]);
    } else {
        int m = qi - NJIT;
        qx = src[3*m + 0]; qy = src[3*m + 1]; qz = src[3*m + 2];
    }
    const float qx2 = -2.0f * qx, qy2 = -2.0f * qy, qz2 = -2.0f * qz;
    const float q2  = fmaf(qx, qx, fmaf(qy, qy, qz * qz));
    const unsigned long long qxp = packf2(qx2, qx2);
    const unsigned long long qyp = packf2(qy2, qy2);
    const unsigned long long qzp = packf2(qz2, qz2);

    int s0 = 0x7F000000, s1 = 0x7F000001, s2 = 0x7F000002,
        s3 = 0x7F000003, s4 = 0x7F000004;
    float thr = __int_as_float(s4) - q2;   // threshold in r-space

    // Broadcast scan: all lanes read the SAME pairs (uniform address ->
    // conflict-free broadcast). This warp covers pairs [quart*256, +256),
    // processing two pairs (4 points) per iteration.
    const ulonglong2* pc = reinterpret_cast<const ulonglong2*>(sC) + (quart << 9);
    const int joff = quart << 9;     // point-index offset = quart*512

#pragma unroll 4
    for (int k = 0; k < QPAIRS / 2; ++k) {
        ulonglong2 A0 = pc[4 * k];        // pair 2k   : {x-pair, y-pair}
        ulonglong2 B0 = pc[4 * k + 1];    //           : {z-pair, w-pair}
        ulonglong2 A1 = pc[4 * k + 2];    // pair 2k+1
        ulonglong2 B1 = pc[4 * k + 3];
        unsigned long long ra, rb;
        asm("fma.rn.f32x2 %0, %1, %2, %3;" : "=l"(ra) : "l"(B0.x), "l"(qzp), "l"(B0.y));
        asm("fma.rn.f32x2 %0, %1, %2, %3;" : "=l"(rb) : "l"(B1.x), "l"(qzp), "l"(B1.y));
        asm("fma.rn.f32x2 %0, %1, %2, %3;" : "=l"(ra) : "l"(A0.y), "l"(qyp), "l"(ra));
        asm("fma.rn.f32x2 %0, %1, %2, %3;" : "=l"(rb) : "l"(A1.y), "l"(qyp), "l"(rb));
        asm("fma.rn.f32x2 %0, %1, %2, %3;" : "=l"(ra) : "l"(A0.x), "l"(qxp), "l"(ra));
        asm("fma.rn.f32x2 %0, %1, %2, %3;" : "=l"(rb) : "l"(A1.x), "l"(qxp), "l"(rb));
        float r0, r1, r2, r3;
        asm("mov.b64 {%0, %1}, %2;" : "=f"(r0), "=f"(r1) : "l"(ra));
        asm("mov.b64 {%0, %1}, %2;" : "=f"(r2), "=f"(r3) : "l"(rb));

        float rmin = fminf(fminf(r0, r1), fminf(r2, r3));
        if (rmin < thr) {
            int jbase = joff + (k << 2);
            if (r0 < thr) {
                float d2 = r0 + q2;
                ins5key((int)((__float_as_uint(d2) & IDXMASK) | (unsigned)jbase), s0, s1, s2, s3, s4);
                thr = __int_as_float(s4) - q2;
            }
            if (r1 < thr) {
                float d2 = r1 + q2;
                ins5key((int)((__float_as_uint(d2) & IDXMASK) | (unsigned)(jbase + 1)), s0, s1, s2, s3, s4);
                thr = __int_as_float(s4) - q2;
            }
            if (r2 < thr) {
                float d2 = r2 + q2;
                ins5key((int)((__float_as_uint(d2) & IDXMASK) | (unsigned)(jbase + 2)), s0, s1, s2, s3, s4);
                thr = __int_as_float(s4) - q2;
            }
            if (r3 < thr) {
                float d2 = r3 + q2;
                ins5key((int)((__float_as_uint(d2) & IDXMASK) | (unsigned)(jbase + 3)), s0, s1, s2, s3, s4);
                thr = __int_as_float(s4) - q2;
            }
        }
    }

    // Cross-warp merge: quarters 1..3 publish their 5 keys; quarter 0 merges.
    if (quart) {
        sKeys[group][quart - 1][0][lane] = s0;
        sKeys[group][quart - 1][1][lane] = s1;
        sKeys[group][quart - 1][2][lane] = s2;
        sKeys[group][quart - 1][3][lane] = s3;
        sKeys[group][quart - 1][4][lane] = s4;
    }
    __syncthreads();

    if (quart == 0) {
#pragma unroll
        for (int w = 0; w < 3; ++w) {
#pragma unroll
            for (int r = 0; r < KNN; ++r) {
                int o = sKeys[group][w][r][lane];
                if (o < s4) ins5key(o, s0, s1, s2, s3, s4);
            }
        }

        // Exact epilogue (same selected key set as R7/R11).
        float aw = 0.f, gx = 0.f, gy = 0.f, gz = 0.f;
        int keys[KNN] = {s0, s1, s2, s3, s4};
#pragma unroll
        for (int kk = 0; kk < KNN; ++kk) {
            int idx = keys[kk] & 2047;
            int pj = idx >> 1, h = idx & 1;
            const float* base = (const float*)&sC[2 * pj];
            float x = base[0 + h], y = base[2 + h], z = base[4 + h];
            float dx = qx - x, dy = qy - y, dz = qz - z;
            float d2 = fmaf(dx, dx, fmaf(dy, dy, dz * dz));
            float w  = 1.0f / (d2 + EPS_D);
            aw += w;
            gx = fmaf(dx, w, gx);
            gy = fmaf(dy, w, gy);
            gz = fmaf(dz, w, gz);
        }
        float inv = 1.0f / aw;
        g_grad[cloud][qi] = make_float4(gx * inv, gy * inv, gz * inv, 0.f);
    }
}

__global__ __launch_bounds__(256)
void combine_kernel()
{
    __shared__ float sh[8];
    const int tid = threadIdx.x;
    const int qi  = blockIdx.x * 256 + tid;

    float4 gT = g_grad[0][qi];
    float4 gS = g_grad[1][qi];

    float axT = gT.x + EPS_N, ayT = gT.y + EPS_N, azT = gT.z + EPS_N;
    float axS = gS.x + EPS_N, ayS = gS.y + EPS_N, azS = gS.z + EPS_N;
    float uT = sqrtf(fmaf(axT, axT, fmaf(ayT, ayT, azT * azT)));
    float uS = sqrtf(fmaf(axS, axS, fmaf(ayS, ayS, azS * azS)));

    float e1 = fabsf(uT - uS);
    float e2 = fabsf(gS.x - gT.x) + fabsf(gS.y - gT.y) + fabsf(gS.z - gT.z);
    float t  = e1 + e2;
    float v  = t * __expf(-BETA * t);

#pragma unroll
    for (int o = 16; o > 0; o >>= 1) v += __shfl_down_sync(0xFFFFFFFFu, v, o);
    if ((tid & 31) == 0) sh[tid >> 5] = v;
    __syncthreads();
    if (tid == 0) {
        float s = 0.f;
#pragma unroll
        for (int w = 0; w < 8; ++w) s += sh[w];
        g_partial[blockIdx.x] = s;
    }
}

__global__ void final_reduce(float* __restrict__ out)
{
    __shared__ float sh[4];
    int tid = threadIdx.x;   // 128
    float v = (tid < NB2) ? g_partial[tid] : 0.f;
#pragma unroll
    for (int o = 16; o > 0; o >>= 1) v += __shfl_down_sync(0xFFFFFFFFu, v, o);
    if ((tid & 31) == 0) sh[tid >> 5] = v;
    __syncthreads();
    if (tid == 0) {
        float s = sh[0] + sh[1] + sh[2] + sh[3];
        out[0] = s * (1.0f / (float)QTOT);
    }
}

extern "C" void kernel_launch(void* const* d_in, const int* in_sizes, int n_in,
                              void* d_out, int out_size)
{
    const float* src   = (const float*)d_in[0];
    const float* tgt   = (const float*)d_in[1];
    const float* noise = (const float*)d_in[2];
    (void)in_sizes; (void)n_in; (void)out_size;

    knn_main<<<dim3(GX1, 2), T1>>>(src, tgt, noise);
    combine_kernel<<<NB2, 256>>>();
    final_reduce<<<1, 128>>>((float*)d_out);
}